// round 6
// baseline (speedup 1.0000x reference)
#include <cuda_runtime.h>
#include <math.h>

#define W 512
#define H 512
#define BATCH 16
#define NPIX (W*H)
#define NMAP (BATCH*NPIX)
#define EPSF 1e-4f

#define NANF __int_as_float(0x7fffffff)

// gray maps for both images: [img][batch][H][W]
__device__ float g_gray[2 * NMAP];
__device__ double g_acc;

// ---------------- smem layout (floats), all strides multiple of 4 ----------------
// gray : 58x58 stride 60  -> 3480   @0        origin (-12,-12)
// sga  : 56x56 stride 56  -> 3136   @3480     origin (-12,-12)  |grad|, NaN outside
// go   : 44x44 stride 44  -> 1936   @6616     origin (-6,-6)    NaN outside
// A    : 4416 @8552 : sg0 48x48 s48 [A] + hs5 48x44 s44 [A+2304]
//                     then h7x 44x38 s40 [A] + h7n [A+1760]
//                     then h7sx 38x32 [A] + h7sn [A+1216]
// B    : 5376 @12968: hmx 56x48 [B] + hmn [B+2688]
//                     then h17a 48x32 [B] + h17b [B+1536]
// C    : 4608 @18344: pmx 48x48 [C] + pmn [C+2304]
//                     then m7x 38x38 s40 [C] + m7n [C+1520]
// D    : 2048 @22952: gmax 32x32 [D] + gmin [D+1024]
#define OFF_GRAY 0
#define OFF_SGA  3480
#define OFF_GO   6616
#define OFF_A    8552
#define OFF_B    12968
#define OFF_C    18344
#define OFF_D    22952
#define SMEM_FLOATS 25000
#define SMEM_BYTES (SMEM_FLOATS * 4)

__global__ void k_zero() { g_acc = 0.0; }

__global__ void k_gray(const float* __restrict__ in, float* __restrict__ outp) {
    int i = blockIdx.x * blockDim.x + threadIdx.x;
    if (i >= NMAP / 4) return;
    int b = i / (NPIX / 4);
    int p = i - b * (NPIX / 4);
    const float4* base = (const float4*)(in + (size_t)b * 3 * NPIX);
    float4 r = base[p];
    float4 g = base[NPIX / 4 + p];
    float4 bl = base[2 * (NPIX / 4) + p];
    float4 o;
    o.x = 0.299f * r.x + 0.587f * g.x + 0.114f * bl.x;
    o.y = 0.299f * r.y + 0.587f * g.y + 0.114f * bl.y;
    o.z = 0.299f * r.z + 0.587f * g.z + 0.114f * bl.z;
    o.w = 0.299f * r.w + 0.587f * g.w + 0.114f * bl.w;
    ((float4*)outp)[i] = o;
}

__global__ __launch_bounds__(1024)
void k_mega(float* __restrict__ out_unused) {
    extern __shared__ float S[];
    __shared__ double sred[32];

    const int b = blockIdx.z;
    const int X0 = blockIdx.x * 32, Y0 = blockIdx.y * 32;
    const int tid = threadIdx.x;

    double acc = 0.0;
    float vsave[2][4];

    #pragma unroll
    for (int img = 0; img < 2; ++img) {
        const float* __restrict__ gp = g_gray + (size_t)img * NMAP + (size_t)b * NPIX;

        __syncthreads();
        // ---- load gray 58x58 @(-12,-12), 0 outside ----
        #pragma unroll
        for (int u = 0; u < 4; ++u) {
            int idx = tid + u * 1024;
            if (idx < 3364) {
                int r = idx / 58, c = idx - r * 58;
                int gy = Y0 - 12 + r, gx = X0 - 12 + c;
                float v = 0.f;
                if ((unsigned)gx < (unsigned)W && (unsigned)gy < (unsigned)H)
                    v = __ldg(gp + gy * W + gx);
                S[OFF_GRAY + r * 60 + c] = v;
            }
        }
        __syncthreads();

        #pragma unroll
        for (int dir = 0; dir < 2; ++dir) {
            // ======== P1: sga (56x56, NaN outside) ; sg0 (48x48, 0 outside) ========
            if (tid < 784) {  // 56 rows x 14 col-groups
                int r = tid / 14, g4 = (tid - r * 14) * 4;
                const float* p = S + OFF_GRAY + r * 60 + g4;
                float4 a = *(const float4*)p;
                float n0, n1, n2, n3;
                if (dir == 0) {
                    float e = p[4];
                    n0 = a.y; n1 = a.z; n2 = a.w; n3 = e;
                } else {
                    float4 bb = *(const float4*)(p + 60);
                    n0 = bb.x; n1 = bb.y; n2 = bb.z; n3 = bb.w;
                }
                int gy = Y0 - 12 + r, gxb = X0 - 12 + g4;
                bool iny = (unsigned)gy < (unsigned)H;
                float4 o;
                o.x = (iny && (unsigned)(gxb + 0) < (unsigned)W) ? fabsf(a.x - n0) : NANF;
                o.y = (iny && (unsigned)(gxb + 1) < (unsigned)W) ? fabsf(a.y - n1) : NANF;
                o.z = (iny && (unsigned)(gxb + 2) < (unsigned)W) ? fabsf(a.z - n2) : NANF;
                o.w = (iny && (unsigned)(gxb + 3) < (unsigned)W) ? fabsf(a.w - n3) : NANF;
                *(float4*)(S + OFF_SGA + r * 56 + g4) = o;
            }
            if (tid < 576) {  // sg0: 48 rows x 12 col-groups, gray offset (+4,+4)
                int r = tid / 12, g4 = (tid - r * 12) * 4;
                const float* p = S + OFF_GRAY + (r + 4) * 60 + g4 + 4;
                float4 a = *(const float4*)p;
                float n0, n1, n2, n3;
                if (dir == 0) {
                    float e = p[4];
                    n0 = a.y; n1 = a.z; n2 = a.w; n3 = e;
                } else {
                    float4 bb = *(const float4*)(p + 60);
                    n0 = bb.x; n1 = bb.y; n2 = bb.z; n3 = bb.w;
                }
                int gy = Y0 - 8 + r, gxb = X0 - 8 + g4;
                bool iny = (unsigned)gy < (unsigned)H;
                float4 o;
                o.x = (iny && (unsigned)(gxb + 0) < (unsigned)W) ? (a.x - n0) : 0.f;
                o.y = (iny && (unsigned)(gxb + 1) < (unsigned)W) ? (a.y - n1) : 0.f;
                o.z = (iny && (unsigned)(gxb + 2) < (unsigned)W) ? (a.z - n2) : 0.f;
                o.w = (iny && (unsigned)(gxb + 3) < (unsigned)W) ? (a.w - n3) : 0.f;
                *(float4*)(S + OFF_A + r * 48 + g4) = o;
            }
            __syncthreads();

            // ======== P2: hmx/hmn (56x48) 9-tap h-max/min ; hs5 (48x44) 5-tap h-sum ========
            if (tid < 672) {  // 56 rows x 12 groups
                int r = tid / 12, g4 = (tid - r * 12) * 4;
                const float* p = S + OFF_SGA + r * 56 + g4;
                float4 A = *(const float4*)p;
                float4 Bv = *(const float4*)(p + 4);
                float4 Cv = *(const float4*)(p + 8);
                float t0=A.x,t1=A.y,t2=A.z,t3=A.w,t4=Bv.x,t5=Bv.y,t6=Bv.z,t7=Bv.w,t8=Cv.x,t9=Cv.y,t10=Cv.z,t11=Cv.w;
                float cx = fmaxf(fmaxf(fmaxf(t3,t4),fmaxf(t5,t6)),fmaxf(t7,t8));
                float cn = fminf(fminf(fminf(t3,t4),fminf(t5,t6)),fminf(t7,t8));
                float4 ox, on;
                ox.x = fmaxf(fmaxf(fmaxf(cx,t0),t1),t2);
                ox.y = fmaxf(fmaxf(fmaxf(cx,t1),t2),t9);
                ox.z = fmaxf(fmaxf(fmaxf(cx,t2),t9),t10);
                ox.w = fmaxf(fmaxf(fmaxf(cx,t9),t10),t11);
                on.x = fminf(fminf(fminf(cn,t0),t1),t2);
                on.y = fminf(fminf(fminf(cn,t1),t2),t9);
                on.z = fminf(fminf(fminf(cn,t2),t9),t10);
                on.w = fminf(fminf(fminf(cn,t9),t10),t11);
                *(float4*)(S + OFF_B + r * 48 + g4) = ox;
                *(float4*)(S + OFF_B + 2688 + r * 48 + g4) = on;
            }
            if (tid < 528) {  // hs5: 48 rows x 11 groups
                int r = tid / 11, g4 = (tid - r * 11) * 4;
                const float* p = S + OFF_A + r * 48 + g4;
                float4 A = *(const float4*)p;
                float4 Bv = *(const float4*)(p + 4);
                float s0 = A.x + A.y + A.z + A.w + Bv.x;
                float s1 = s0 - A.x + Bv.y;
                float s2 = s1 - A.y + Bv.z;
                float s3 = s2 - A.z + Bv.w;
                *(float4*)(S + OFF_A + 2304 + r * 44 + g4) = make_float4(s0, s1, s2, s3);
            }
            __syncthreads();

            // ======== P3: pm (48x48 v-max/min, masked 0 outside) ; go (44x44) ========
            if (tid < 576) {  // 12 row-groups x 48 cols
                int rg = tid / 48, c = tid - rg * 48;
                int r4 = rg * 4;
                int gx = X0 - 8 + c;
                bool inx = (unsigned)gx < (unsigned)W;
                int gyb = Y0 - 8 + r4;
                bool i0 = inx && (unsigned)(gyb + 0) < (unsigned)H;
                bool i1 = inx && (unsigned)(gyb + 1) < (unsigned)H;
                bool i2 = inx && (unsigned)(gyb + 2) < (unsigned)H;
                bool i3 = inx && (unsigned)(gyb + 3) < (unsigned)H;
                {
                    float t[12];
                    #pragma unroll
                    for (int q = 0; q < 12; ++q) t[q] = S[OFF_B + (r4 + q) * 48 + c];
                    float cx = fmaxf(fmaxf(fmaxf(t[3],t[4]),fmaxf(t[5],t[6])),fmaxf(t[7],t[8]));
                    float o0 = fmaxf(fmaxf(fmaxf(cx,t[0]),t[1]),t[2]);
                    float o1 = fmaxf(fmaxf(fmaxf(cx,t[1]),t[2]),t[9]);
                    float o2 = fmaxf(fmaxf(fmaxf(cx,t[2]),t[9]),t[10]);
                    float o3 = fmaxf(fmaxf(fmaxf(cx,t[9]),t[10]),t[11]);
                    S[OFF_C + (r4 + 0) * 48 + c] = i0 ? o0 : 0.f;
                    S[OFF_C + (r4 + 1) * 48 + c] = i1 ? o1 : 0.f;
                    S[OFF_C + (r4 + 2) * 48 + c] = i2 ? o2 : 0.f;
                    S[OFF_C + (r4 + 3) * 48 + c] = i3 ? o3 : 0.f;
                }
                {
                    float t[12];
                    #pragma unroll
                    for (int q = 0; q < 12; ++q) t[q] = S[OFF_B + 2688 + (r4 + q) * 48 + c];
                    float cn = fminf(fminf(fminf(t[3],t[4]),fminf(t[5],t[6])),fminf(t[7],t[8]));
                    float o0 = fminf(fminf(fminf(cn,t[0]),t[1]),t[2]);
                    float o1 = fminf(fminf(fminf(cn,t[1]),t[2]),t[9]);
                    float o2 = fminf(fminf(fminf(cn,t[2]),t[9]),t[10]);
                    float o3 = fminf(fminf(fminf(cn,t[9]),t[10]),t[11]);
                    S[OFF_C + 2304 + (r4 + 0) * 48 + c] = i0 ? o0 : 0.f;
                    S[OFF_C + 2304 + (r4 + 1) * 48 + c] = i1 ? o1 : 0.f;
                    S[OFF_C + 2304 + (r4 + 2) * 48 + c] = i2 ? o2 : 0.f;
                    S[OFF_C + 2304 + (r4 + 3) * 48 + c] = i3 ? o3 : 0.f;
                }
            }
            if (tid < 484) {  // go: 11 row-groups x 44 cols
                int rg = tid / 44, c = tid - rg * 44;
                int r4 = rg * 4;
                float t[8];
                #pragma unroll
                for (int q = 0; q < 8; ++q) t[q] = S[OFF_A + 2304 + (r4 + q) * 44 + c];
                float s0 = t[0] + t[1] + t[2] + t[3] + t[4];
                float s1 = s0 - t[0] + t[5];
                float s2 = s1 - t[1] + t[6];
                float s3 = s2 - t[2] + t[7];
                float ss[4] = { s0, s1, s2, s3 };
                int gx = X0 - 6 + c;
                float cntx = (float)(min(gx + 2, W - 1) - max(gx - 2, 0) + 1);
                #pragma unroll
                for (int j = 0; j < 4; ++j) {
                    int gy = Y0 - 6 + r4 + j;
                    float v = NANF;
                    if ((unsigned)gx < (unsigned)W && (unsigned)gy < (unsigned)H) {
                        float cnty = (float)(min(gy + 2, H - 1) - max(gy - 2, 0) + 1);
                        v = fabsf(__fdividef(ss[j], cntx * cnty));
                    }
                    S[OFF_GO + (r4 + j) * 44 + c] = v;
                }
            }
            __syncthreads();

            // ======== P4: h17 (48x32) from pm ; h7 (44x38) from go ========
            if (tid < 384) {  // h17: 48 rows x 8 groups
                int r = tid / 8, g4 = (tid & 7) * 4;
                {
                    const float* p = S + OFF_C + r * 48 + g4;
                    float t[20];
                    #pragma unroll
                    for (int q = 0; q < 5; ++q) {
                        float4 v = *(const float4*)(p + q * 4);
                        t[q*4] = v.x; t[q*4+1] = v.y; t[q*4+2] = v.z; t[q*4+3] = v.w;
                    }
                    float s0 = 0.f;
                    #pragma unroll
                    for (int q = 0; q < 17; ++q) s0 += t[q];
                    float s1 = s0 - t[0] + t[17];
                    float s2 = s1 - t[1] + t[18];
                    float s3 = s2 - t[2] + t[19];
                    *(float4*)(S + OFF_B + r * 32 + g4) = make_float4(s0, s1, s2, s3);
                }
                {
                    const float* p = S + OFF_C + 2304 + r * 48 + g4;
                    float t[20];
                    #pragma unroll
                    for (int q = 0; q < 5; ++q) {
                        float4 v = *(const float4*)(p + q * 4);
                        t[q*4] = v.x; t[q*4+1] = v.y; t[q*4+2] = v.z; t[q*4+3] = v.w;
                    }
                    float s0 = 0.f;
                    #pragma unroll
                    for (int q = 0; q < 17; ++q) s0 += t[q];
                    float s1 = s0 - t[0] + t[17];
                    float s2 = s1 - t[1] + t[18];
                    float s3 = s2 - t[2] + t[19];
                    *(float4*)(S + OFF_B + 1536 + r * 32 + g4) = make_float4(s0, s1, s2, s3);
                }
            }
            if (tid < 440) {  // h7: 44 rows x 10 groups (last group cols 36,37 via overlap)
                int r = tid / 10, g = tid - r * 10;
                if (g < 9) {
                    int g4 = g * 4;
                    const float* p = S + OFF_GO + r * 44 + g4;
                    float4 A = *(const float4*)p;
                    float4 Bv = *(const float4*)(p + 4);
                    float4 Cv = *(const float4*)(p + 8);
                    float t0=A.x,t1=A.y,t2=A.z,t3=A.w,t4=Bv.x,t5=Bv.y,t6=Bv.z,t7=Bv.w,t8=Cv.x,t9=Cv.y;
                    float cx = fmaxf(fmaxf(t3,t4),fmaxf(t5,t6));
                    float cn = fminf(fminf(t3,t4),fminf(t5,t6));
                    float4 ox, on;
                    ox.x = fmaxf(fmaxf(fmaxf(cx,t0),t1),t2);
                    ox.y = fmaxf(fmaxf(fmaxf(cx,t1),t2),t7);
                    ox.z = fmaxf(fmaxf(fmaxf(cx,t2),t7),t8);
                    ox.w = fmaxf(fmaxf(fmaxf(cx,t7),t8),t9);
                    on.x = fminf(fminf(fminf(cn,t0),t1),t2);
                    on.y = fminf(fminf(fminf(cn,t1),t2),t7);
                    on.z = fminf(fminf(fminf(cn,t2),t7),t8);
                    on.w = fminf(fminf(fminf(cn,t7),t8),t9);
                    *(float4*)(S + OFF_A + r * 40 + g4) = ox;
                    *(float4*)(S + OFF_A + 1760 + r * 40 + g4) = on;
                } else {
                    // cols 36,37 : windows go[36..42], go[37..43]
                    const float* p = S + OFF_GO + r * 44 + 36;
                    float4 A = *(const float4*)p;          // 36..39
                    float4 Bv = *(const float4*)(p + 4);   // 40..43
                    float t0=A.x,t1=A.y,t2=A.z,t3=A.w,t4=Bv.x,t5=Bv.y,t6=Bv.z,t7=Bv.w;
                    float c6x = fmaxf(fmaxf(t1,t2),fmaxf(fmaxf(t3,t4),fmaxf(t5,t6)));
                    float c6n = fminf(fminf(t1,t2),fminf(fminf(t3,t4),fminf(t5,t6)));
                    S[OFF_A + r * 40 + 36] = fmaxf(c6x, t0);
                    S[OFF_A + r * 40 + 37] = fmaxf(c6x, t7);
                    S[OFF_A + 1760 + r * 40 + 36] = fminf(c6n, t0);
                    S[OFF_A + 1760 + r * 40 + 37] = fminf(c6n, t7);
                }
            }
            __syncthreads();

            // ======== P5: m7 (38x38 v, masked 0 outside) ; gmax/gmin (32x32) ========
            if (tid < 380) {  // 10 row-groups x 38 cols (last group rows 34..37 overlap)
                int rg = tid / 38, c = tid - rg * 38;
                int r0 = min(rg * 4, 34);
                int gx = X0 - 3 + c;
                bool inx = (unsigned)gx < (unsigned)W;
                int gyb = Y0 - 3 + r0;
                bool i0 = inx && (unsigned)(gyb + 0) < (unsigned)H;
                bool i1 = inx && (unsigned)(gyb + 1) < (unsigned)H;
                bool i2 = inx && (unsigned)(gyb + 2) < (unsigned)H;
                bool i3 = inx && (unsigned)(gyb + 3) < (unsigned)H;
                {
                    float t[10];
                    #pragma unroll
                    for (int q = 0; q < 10; ++q) t[q] = S[OFF_A + (r0 + q) * 40 + c];
                    float cx = fmaxf(fmaxf(t[3],t[4]),fmaxf(t[5],t[6]));
                    float o0 = fmaxf(fmaxf(fmaxf(cx,t[0]),t[1]),t[2]);
                    float o1 = fmaxf(fmaxf(fmaxf(cx,t[1]),t[2]),t[7]);
                    float o2 = fmaxf(fmaxf(fmaxf(cx,t[2]),t[7]),t[8]);
                    float o3 = fmaxf(fmaxf(fmaxf(cx,t[7]),t[8]),t[9]);
                    S[OFF_C + (r0 + 0) * 40 + c] = i0 ? o0 : 0.f;
                    S[OFF_C + (r0 + 1) * 40 + c] = i1 ? o1 : 0.f;
                    S[OFF_C + (r0 + 2) * 40 + c] = i2 ? o2 : 0.f;
                    S[OFF_C + (r0 + 3) * 40 + c] = i3 ? o3 : 0.f;
                }
                {
                    float t[10];
                    #pragma unroll
                    for (int q = 0; q < 10; ++q) t[q] = S[OFF_A + 1760 + (r0 + q) * 40 + c];
                    float cn = fminf(fminf(t[3],t[4]),fminf(t[5],t[6]));
                    float o0 = fminf(fminf(fminf(cn,t[0]),t[1]),t[2]);
                    float o1 = fminf(fminf(fminf(cn,t[1]),t[2]),t[7]);
                    float o2 = fminf(fminf(fminf(cn,t[2]),t[7]),t[8]);
                    float o3 = fminf(fminf(fminf(cn,t[7]),t[8]),t[9]);
                    S[OFF_C + 1520 + (r0 + 0) * 40 + c] = i0 ? o0 : 0.f;
                    S[OFF_C + 1520 + (r0 + 1) * 40 + c] = i1 ? o1 : 0.f;
                    S[OFF_C + 1520 + (r0 + 2) * 40 + c] = i2 ? o2 : 0.f;
                    S[OFF_C + 1520 + (r0 + 3) * 40 + c] = i3 ? o3 : 0.f;
                }
            }
            if (tid < 256) {  // v17: 8 row-groups x 32 cols -> gmax/gmin
                int rg = tid >> 5, c = tid & 31;
                int r0 = rg * 4;
                int gx = X0 + c;
                float cntx = (float)(min(gx + 8, W - 1) - max(gx - 8, 0) + 1);
                float inv[4];
                #pragma unroll
                for (int j = 0; j < 4; ++j) {
                    int gy = Y0 + r0 + j;
                    float cnty = (float)(min(gy + 8, H - 1) - max(gy - 8, 0) + 1);
                    inv[j] = __fdividef(1.f, cntx * cnty);
                }
                {
                    float t[20];
                    #pragma unroll
                    for (int q = 0; q < 20; ++q) t[q] = S[OFF_B + (r0 + q) * 32 + c];
                    float s0 = 0.f;
                    #pragma unroll
                    for (int q = 0; q < 17; ++q) s0 += t[q];
                    float s1 = s0 - t[0] + t[17];
                    float s2 = s1 - t[1] + t[18];
                    float s3 = s2 - t[2] + t[19];
                    S[OFF_D + (r0 + 0) * 32 + c] = s0 * inv[0];
                    S[OFF_D + (r0 + 1) * 32 + c] = s1 * inv[1];
                    S[OFF_D + (r0 + 2) * 32 + c] = s2 * inv[2];
                    S[OFF_D + (r0 + 3) * 32 + c] = s3 * inv[3];
                }
                {
                    float t[20];
                    #pragma unroll
                    for (int q = 0; q < 20; ++q) t[q] = S[OFF_B + 1536 + (r0 + q) * 32 + c];
                    float s0 = 0.f;
                    #pragma unroll
                    for (int q = 0; q < 17; ++q) s0 += t[q];
                    float s1 = s0 - t[0] + t[17];
                    float s2 = s1 - t[1] + t[18];
                    float s3 = s2 - t[2] + t[19];
                    S[OFF_D + 1024 + (r0 + 0) * 32 + c] = s0 * inv[0];
                    S[OFF_D + 1024 + (r0 + 1) * 32 + c] = s1 * inv[1];
                    S[OFF_D + 1024 + (r0 + 2) * 32 + c] = s2 * inv[2];
                    S[OFF_D + 1024 + (r0 + 3) * 32 + c] = s3 * inv[3];
                }
            }
            __syncthreads();

            // ======== P6: h7s (38x32) 7-tap h-sum of m7 ========
            if (tid < 304) {  // 38 rows x 8 groups
                int r = tid / 8, g4 = (tid & 7) * 4;
                {
                    const float* p = S + OFF_C + r * 40 + g4;
                    float4 A = *(const float4*)p;
                    float4 Bv = *(const float4*)(p + 4);
                    float4 Cv = *(const float4*)(p + 8);  // cols g4+8..g4+11 (<=39, padded stride; t10,t11 unused)
                    float t0=A.x,t1=A.y,t2=A.z,t3=A.w,t4=Bv.x,t5=Bv.y,t6=Bv.z,t7=Bv.w,t8=Cv.x,t9=Cv.y;
                    float s0 = t0+t1+t2+t3+t4+t5+t6;
                    float s1 = s0 - t0 + t7;
                    float s2 = s1 - t1 + t8;
                    float s3 = s2 - t2 + t9;
                    *(float4*)(S + OFF_A + r * 32 + g4) = make_float4(s0, s1, s2, s3);
                }
                {
                    const float* p = S + OFF_C + 1520 + r * 40 + g4;
                    float4 A = *(const float4*)p;
                    float4 Bv = *(const float4*)(p + 4);
                    float4 Cv = *(const float4*)(p + 8);
                    float t0=A.x,t1=A.y,t2=A.z,t3=A.w,t4=Bv.x,t5=Bv.y,t6=Bv.z,t7=Bv.w,t8=Cv.x,t9=Cv.y;
                    float s0 = t0+t1+t2+t3+t4+t5+t6;
                    float s1 = s0 - t0 + t7;
                    float s2 = s1 - t1 + t8;
                    float s3 = s2 - t2 + t9;
                    *(float4*)(S + OFF_A + 1216 + r * 32 + g4) = make_float4(s0, s1, s2, s3);
                }
            }
            __syncthreads();

            // ======== P7: final (32x32), 4 rows/thread ========
            if (tid < 256) {
                int rg = tid >> 5, c = tid & 31;
                int r0 = rg * 4;
                float sA[4], sD[4];
                {
                    float t[10];
                    #pragma unroll
                    for (int q = 0; q < 10; ++q) t[q] = S[OFF_A + (r0 + q) * 32 + c];
                    sA[0] = t[0]+t[1]+t[2]+t[3]+t[4]+t[5]+t[6];
                    sA[1] = sA[0] - t[0] + t[7];
                    sA[2] = sA[1] - t[1] + t[8];
                    sA[3] = sA[2] - t[2] + t[9];
                }
                {
                    float t[10];
                    #pragma unroll
                    for (int q = 0; q < 10; ++q) t[q] = S[OFF_A + 1216 + (r0 + q) * 32 + c];
                    sD[0] = t[0]+t[1]+t[2]+t[3]+t[4]+t[5]+t[6];
                    sD[1] = sD[0] - t[0] + t[7];
                    sD[2] = sD[1] - t[1] + t[8];
                    sD[3] = sD[2] - t[2] + t[9];
                }
                int gx = X0 + c;
                float cntx = (float)(min(gx + 3, W - 1) - max(gx - 3, 0) + 1);
                #pragma unroll
                for (int j = 0; j < 4; ++j) {
                    int gy = Y0 + r0 + j;
                    float cnty = (float)(min(gy + 3, H - 1) - max(gy - 3, 0) + 1);
                    float inv = __fdividef(1.f, cntx * cnty);
                    float pmax = sA[j] * inv, pmin = sD[j] * inv;
                    float go = S[OFF_GO + (r0 + j + 6) * 44 + c + 6];
                    float ga = S[OFF_SGA + (r0 + j + 12) * 56 + c + 12];
                    float gmax = S[OFF_D + (r0 + j) * 32 + c];
                    float gmin = S[OFF_D + 1024 + (r0 + j) * 32 + c];
                    float gn = __fdividef(go - pmin, fabsf(pmax - pmin) + EPSF);
                    float gn1 = __fdividef(ga - gmin, fabsf(gmax - gmin) + EPSF);
                    float val = (gn + 0.01f) * gn1;
                    if (img == 0) {
                        vsave[dir][j] = val;
                    } else {
                        float rv = vsave[dir][j];
                        acc += (double)(rv * expf(-10.f * (rv + val)));
                    }
                }
            }
            __syncthreads();
        }
    }

    // ---- block reduction ----
    int tx = tid & 31, ty = tid >> 5;
    #pragma unroll
    for (int off = 16; off; off >>= 1) acc += __shfl_down_sync(0xffffffffu, acc, off);
    if (tx == 0) sred[ty] = acc;
    __syncthreads();
    if (ty == 0) {
        double w = sred[tx];
        #pragma unroll
        for (int off = 16; off; off >>= 1) w += __shfl_down_sync(0xffffffffu, w, off);
        if (tx == 0) atomicAdd(&g_acc, w);
    }
}

__global__ void k_out(float* __restrict__ out) {
    out[0] = (float)(g_acc / (double)NMAP);
}

extern "C" void kernel_launch(void* const* d_in, const int* in_sizes, int n_in,
                              void* d_out, int out_size) {
    const float* R_low = (const float*)d_in[0];
    const float* low = (const float*)d_in[1];
    float* out = (float*)d_out;

    cudaFuncSetAttribute(k_mega, cudaFuncAttributeMaxDynamicSharedMemorySize, SMEM_BYTES);

    float* grayR;
    float* grayL;
    cudaGetSymbolAddress((void**)&grayR, g_gray);
    grayL = grayR + NMAP;

    int gray_blocks = (NMAP / 4 + 255) / 256;

    k_zero<<<1, 1>>>();
    k_gray<<<gray_blocks, 256>>>(R_low, grayR);
    k_gray<<<gray_blocks, 256>>>(low, grayL);

    dim3 grd(16, 16, 16);
    k_mega<<<grd, 1024, SMEM_BYTES>>>(out);

    k_out<<<1, 1>>>(out);
}

// round 7
// speedup vs baseline: 2.1173x; 2.1173x over previous
#include <cuda_runtime.h>
#include <math.h>

#define W 512
#define H 512
#define BATCH 16
#define NPIX (W*H)
#define NMAP (BATCH*NPIX)
#define EPSF 1e-4f
#define NT 512

#define NANF __int_as_float(0x7fffffff)

__device__ float g_gray[2 * NMAP];
__device__ double g_acc;

// ---------------- smem layout (floats), strides multiple of 4 ----------------
// gray : 58x58 s60 -> 3480 @0       origin (-12,-12)
// sga  : 56x56 s56 -> 3136 @3480    |grad|, NaN outside
// go   : 44x44 s44 -> 1936 @6616    NaN outside
// A    : 4416 @8552 : sg0 48x48 s48 + hs5 48x44 s44 [A+2304]
//                     then h7x 44x38 s40 [A] + h7n [A+1760]
//                     then h7sx 38x32 [A] + h7sn [A+1216]
// B    : 5376 @12968: hmx 56x48 [B] + hmn [B+2688]
//                     then h17a 48x32 [B] + h17b [B+1536]
// C    : 4608 @18344: pmx 48x48 [C] + pmn [C+2304]
//                     then m7x 38x38 s40 [C] + m7n [C+1520]
#define OFF_GRAY 0
#define OFF_SGA  3480
#define OFF_GO   6616
#define OFF_A    8552
#define OFF_B    12968
#define OFF_C    18344
#define SMEM_FLOATS 22952
#define SMEM_BYTES (SMEM_FLOATS * 4)

__global__ void k_zero() { g_acc = 0.0; }

__global__ void k_gray(const float* __restrict__ in, float* __restrict__ outp) {
    int i = blockIdx.x * blockDim.x + threadIdx.x;
    if (i >= NMAP / 4) return;
    int b = i / (NPIX / 4);
    int p = i - b * (NPIX / 4);
    const float4* base = (const float4*)(in + (size_t)b * 3 * NPIX);
    float4 r = base[p];
    float4 g = base[NPIX / 4 + p];
    float4 bl = base[2 * (NPIX / 4) + p];
    float4 o;
    o.x = 0.299f * r.x + 0.587f * g.x + 0.114f * bl.x;
    o.y = 0.299f * r.y + 0.587f * g.y + 0.114f * bl.y;
    o.z = 0.299f * r.z + 0.587f * g.z + 0.114f * bl.z;
    o.w = 0.299f * r.w + 0.587f * g.w + 0.114f * bl.w;
    ((float4*)outp)[i] = o;
}

__global__ __launch_bounds__(NT, 2)
void k_mega() {
    extern __shared__ float S[];
    __shared__ double sred[NT / 32];

    const int b = blockIdx.z;
    const int X0 = blockIdx.x * 32, Y0 = blockIdx.y * 32;
    const int tid = threadIdx.x;

    double acc = 0.0;
    float vsave[2][4];
    float gmv[4], gnv[4];   // gmax1/gmin1 kept in registers (tid<256 threads)

    #pragma unroll
    for (int img = 0; img < 2; ++img) {
        const float* __restrict__ gp = g_gray + (size_t)img * NMAP + (size_t)b * NPIX;

        __syncthreads();
        // ---- load gray 58x58 @(-12,-12), 0 outside ----
        for (int idx = tid; idx < 3364; idx += NT) {
            int r = idx / 58, c = idx - r * 58;
            int gy = Y0 - 12 + r, gx = X0 - 12 + c;
            float v = 0.f;
            if ((unsigned)gx < (unsigned)W && (unsigned)gy < (unsigned)H)
                v = __ldg(gp + gy * W + gx);
            S[OFF_GRAY + r * 60 + c] = v;
        }
        __syncthreads();

        #pragma unroll
        for (int dir = 0; dir < 2; ++dir) {
            // ======== P1: sga (56x56, NaN outside) ; sg0 (48x48, 0 outside) ========
            #pragma unroll
            for (int idx = tid; idx < 784; idx += NT) {  // 56 rows x 14 groups
                int r = idx / 14, g4 = (idx - r * 14) * 4;
                const float* p = S + OFF_GRAY + r * 60 + g4;
                float4 a = *(const float4*)p;
                float n0, n1, n2, n3;
                if (dir == 0) {
                    float e = p[4];
                    n0 = a.y; n1 = a.z; n2 = a.w; n3 = e;
                } else {
                    float4 bb = *(const float4*)(p + 60);
                    n0 = bb.x; n1 = bb.y; n2 = bb.z; n3 = bb.w;
                }
                int gy = Y0 - 12 + r, gxb = X0 - 12 + g4;
                bool iny = (unsigned)gy < (unsigned)H;
                float4 o;
                o.x = (iny && (unsigned)(gxb + 0) < (unsigned)W) ? fabsf(a.x - n0) : NANF;
                o.y = (iny && (unsigned)(gxb + 1) < (unsigned)W) ? fabsf(a.y - n1) : NANF;
                o.z = (iny && (unsigned)(gxb + 2) < (unsigned)W) ? fabsf(a.z - n2) : NANF;
                o.w = (iny && (unsigned)(gxb + 3) < (unsigned)W) ? fabsf(a.w - n3) : NANF;
                *(float4*)(S + OFF_SGA + r * 56 + g4) = o;
            }
            #pragma unroll
            for (int idx = tid; idx < 576; idx += NT) {  // 48 rows x 12 groups
                int r = idx / 12, g4 = (idx - r * 12) * 4;
                const float* p = S + OFF_GRAY + (r + 4) * 60 + g4 + 4;
                float4 a = *(const float4*)p;
                float n0, n1, n2, n3;
                if (dir == 0) {
                    float e = p[4];
                    n0 = a.y; n1 = a.z; n2 = a.w; n3 = e;
                } else {
                    float4 bb = *(const float4*)(p + 60);
                    n0 = bb.x; n1 = bb.y; n2 = bb.z; n3 = bb.w;
                }
                int gy = Y0 - 8 + r, gxb = X0 - 8 + g4;
                bool iny = (unsigned)gy < (unsigned)H;
                float4 o;
                o.x = (iny && (unsigned)(gxb + 0) < (unsigned)W) ? (a.x - n0) : 0.f;
                o.y = (iny && (unsigned)(gxb + 1) < (unsigned)W) ? (a.y - n1) : 0.f;
                o.z = (iny && (unsigned)(gxb + 2) < (unsigned)W) ? (a.z - n2) : 0.f;
                o.w = (iny && (unsigned)(gxb + 3) < (unsigned)W) ? (a.w - n3) : 0.f;
                *(float4*)(S + OFF_A + r * 48 + g4) = o;
            }
            __syncthreads();

            // ======== P2: hmx/hmn (56x48) ; hs5 (48x44) ========
            #pragma unroll
            for (int idx = tid; idx < 672; idx += NT) {  // 56 rows x 12 groups
                int r = idx / 12, g4 = (idx - r * 12) * 4;
                const float* p = S + OFF_SGA + r * 56 + g4;
                float4 A = *(const float4*)p;
                float4 Bv = *(const float4*)(p + 4);
                float4 Cv = *(const float4*)(p + 8);
                float t0=A.x,t1=A.y,t2=A.z,t3=A.w,t4=Bv.x,t5=Bv.y,t6=Bv.z,t7=Bv.w,t8=Cv.x,t9=Cv.y,t10=Cv.z,t11=Cv.w;
                float cx = fmaxf(fmaxf(fmaxf(t3,t4),fmaxf(t5,t6)),fmaxf(t7,t8));
                float cn = fminf(fminf(fminf(t3,t4),fminf(t5,t6)),fminf(t7,t8));
                float4 ox, on;
                ox.x = fmaxf(fmaxf(fmaxf(cx,t0),t1),t2);
                ox.y = fmaxf(fmaxf(fmaxf(cx,t1),t2),t9);
                ox.z = fmaxf(fmaxf(fmaxf(cx,t2),t9),t10);
                ox.w = fmaxf(fmaxf(fmaxf(cx,t9),t10),t11);
                on.x = fminf(fminf(fminf(cn,t0),t1),t2);
                on.y = fminf(fminf(fminf(cn,t1),t2),t9);
                on.z = fminf(fminf(fminf(cn,t2),t9),t10);
                on.w = fminf(fminf(fminf(cn,t9),t10),t11);
                *(float4*)(S + OFF_B + r * 48 + g4) = ox;
                *(float4*)(S + OFF_B + 2688 + r * 48 + g4) = on;
            }
            #pragma unroll
            for (int idx = tid; idx < 528; idx += NT) {  // 48 rows x 11 groups
                int r = idx / 11, g4 = (idx - r * 11) * 4;
                const float* p = S + OFF_A + r * 48 + g4;
                float4 A = *(const float4*)p;
                float4 Bv = *(const float4*)(p + 4);
                float s0 = A.x + A.y + A.z + A.w + Bv.x;
                float s1 = s0 - A.x + Bv.y;
                float s2 = s1 - A.y + Bv.z;
                float s3 = s2 - A.z + Bv.w;
                *(float4*)(S + OFF_A + 2304 + r * 44 + g4) = make_float4(s0, s1, s2, s3);
            }
            __syncthreads();

            // ======== P3: pm (48x48 v, masked 0 outside) ; go (44x44) ========
            #pragma unroll
            for (int idx = tid; idx < 576; idx += NT) {  // 12 row-groups x 48 cols
                int rg = idx / 48, c = idx - rg * 48;
                int r4 = rg * 4;
                int gx = X0 - 8 + c;
                bool inx = (unsigned)gx < (unsigned)W;
                int gyb = Y0 - 8 + r4;
                bool i0 = inx && (unsigned)(gyb + 0) < (unsigned)H;
                bool i1 = inx && (unsigned)(gyb + 1) < (unsigned)H;
                bool i2 = inx && (unsigned)(gyb + 2) < (unsigned)H;
                bool i3 = inx && (unsigned)(gyb + 3) < (unsigned)H;
                {
                    float t[12];
                    #pragma unroll
                    for (int q = 0; q < 12; ++q) t[q] = S[OFF_B + (r4 + q) * 48 + c];
                    float cx = fmaxf(fmaxf(fmaxf(t[3],t[4]),fmaxf(t[5],t[6])),fmaxf(t[7],t[8]));
                    float o0 = fmaxf(fmaxf(fmaxf(cx,t[0]),t[1]),t[2]);
                    float o1 = fmaxf(fmaxf(fmaxf(cx,t[1]),t[2]),t[9]);
                    float o2 = fmaxf(fmaxf(fmaxf(cx,t[2]),t[9]),t[10]);
                    float o3 = fmaxf(fmaxf(fmaxf(cx,t[9]),t[10]),t[11]);
                    S[OFF_C + (r4 + 0) * 48 + c] = i0 ? o0 : 0.f;
                    S[OFF_C + (r4 + 1) * 48 + c] = i1 ? o1 : 0.f;
                    S[OFF_C + (r4 + 2) * 48 + c] = i2 ? o2 : 0.f;
                    S[OFF_C + (r4 + 3) * 48 + c] = i3 ? o3 : 0.f;
                }
                {
                    float t[12];
                    #pragma unroll
                    for (int q = 0; q < 12; ++q) t[q] = S[OFF_B + 2688 + (r4 + q) * 48 + c];
                    float cn = fminf(fminf(fminf(t[3],t[4]),fminf(t[5],t[6])),fminf(t[7],t[8]));
                    float o0 = fminf(fminf(fminf(cn,t[0]),t[1]),t[2]);
                    float o1 = fminf(fminf(fminf(cn,t[1]),t[2]),t[9]);
                    float o2 = fminf(fminf(fminf(cn,t[2]),t[9]),t[10]);
                    float o3 = fminf(fminf(fminf(cn,t[9]),t[10]),t[11]);
                    S[OFF_C + 2304 + (r4 + 0) * 48 + c] = i0 ? o0 : 0.f;
                    S[OFF_C + 2304 + (r4 + 1) * 48 + c] = i1 ? o1 : 0.f;
                    S[OFF_C + 2304 + (r4 + 2) * 48 + c] = i2 ? o2 : 0.f;
                    S[OFF_C + 2304 + (r4 + 3) * 48 + c] = i3 ? o3 : 0.f;
                }
            }
            #pragma unroll
            for (int idx = tid; idx < 484; idx += NT) {  // 11 row-groups x 44 cols
                int rg = idx / 44, c = idx - rg * 44;
                int r4 = rg * 4;
                float t[8];
                #pragma unroll
                for (int q = 0; q < 8; ++q) t[q] = S[OFF_A + 2304 + (r4 + q) * 44 + c];
                float s0 = t[0] + t[1] + t[2] + t[3] + t[4];
                float s1 = s0 - t[0] + t[5];
                float s2 = s1 - t[1] + t[6];
                float s3 = s2 - t[2] + t[7];
                float ss[4] = { s0, s1, s2, s3 };
                int gx = X0 - 6 + c;
                float cntx = (float)(min(gx + 2, W - 1) - max(gx - 2, 0) + 1);
                #pragma unroll
                for (int j = 0; j < 4; ++j) {
                    int gy = Y0 - 6 + r4 + j;
                    float v = NANF;
                    if ((unsigned)gx < (unsigned)W && (unsigned)gy < (unsigned)H) {
                        float cnty = (float)(min(gy + 2, H - 1) - max(gy - 2, 0) + 1);
                        v = fabsf(__fdividef(ss[j], cntx * cnty));
                    }
                    S[OFF_GO + (r4 + j) * 44 + c] = v;
                }
            }
            __syncthreads();

            // ======== P4: h17 (48x32) ; h7 (44x38) ========
            #pragma unroll
            for (int idx = tid; idx < 384; idx += NT) {  // 48 rows x 8 groups
                int r = idx / 8, g4 = (idx & 7) * 4;
                {
                    const float* p = S + OFF_C + r * 48 + g4;
                    float t[20];
                    #pragma unroll
                    for (int q = 0; q < 5; ++q) {
                        float4 v = *(const float4*)(p + q * 4);
                        t[q*4] = v.x; t[q*4+1] = v.y; t[q*4+2] = v.z; t[q*4+3] = v.w;
                    }
                    float s0 = 0.f;
                    #pragma unroll
                    for (int q = 0; q < 17; ++q) s0 += t[q];
                    float s1 = s0 - t[0] + t[17];
                    float s2 = s1 - t[1] + t[18];
                    float s3 = s2 - t[2] + t[19];
                    *(float4*)(S + OFF_B + r * 32 + g4) = make_float4(s0, s1, s2, s3);
                }
                {
                    const float* p = S + OFF_C + 2304 + r * 48 + g4;
                    float t[20];
                    #pragma unroll
                    for (int q = 0; q < 5; ++q) {
                        float4 v = *(const float4*)(p + q * 4);
                        t[q*4] = v.x; t[q*4+1] = v.y; t[q*4+2] = v.z; t[q*4+3] = v.w;
                    }
                    float s0 = 0.f;
                    #pragma unroll
                    for (int q = 0; q < 17; ++q) s0 += t[q];
                    float s1 = s0 - t[0] + t[17];
                    float s2 = s1 - t[1] + t[18];
                    float s3 = s2 - t[2] + t[19];
                    *(float4*)(S + OFF_B + 1536 + r * 32 + g4) = make_float4(s0, s1, s2, s3);
                }
            }
            #pragma unroll
            for (int idx = tid; idx < 440; idx += NT) {  // 44 rows x 10 groups
                int r = idx / 10, g = idx - r * 10;
                if (g < 9) {
                    int g4 = g * 4;
                    const float* p = S + OFF_GO + r * 44 + g4;
                    float4 A = *(const float4*)p;
                    float4 Bv = *(const float4*)(p + 4);
                    float4 Cv = *(const float4*)(p + 8);
                    float t0=A.x,t1=A.y,t2=A.z,t3=A.w,t4=Bv.x,t5=Bv.y,t6=Bv.z,t7=Bv.w,t8=Cv.x,t9=Cv.y;
                    float cx = fmaxf(fmaxf(t3,t4),fmaxf(t5,t6));
                    float cn = fminf(fminf(t3,t4),fminf(t5,t6));
                    float4 ox, on;
                    ox.x = fmaxf(fmaxf(fmaxf(cx,t0),t1),t2);
                    ox.y = fmaxf(fmaxf(fmaxf(cx,t1),t2),t7);
                    ox.z = fmaxf(fmaxf(fmaxf(cx,t2),t7),t8);
                    ox.w = fmaxf(fmaxf(fmaxf(cx,t7),t8),t9);
                    on.x = fminf(fminf(fminf(cn,t0),t1),t2);
                    on.y = fminf(fminf(fminf(cn,t1),t2),t7);
                    on.z = fminf(fminf(fminf(cn,t2),t7),t8);
                    on.w = fminf(fminf(fminf(cn,t7),t8),t9);
                    *(float4*)(S + OFF_A + r * 40 + g4) = ox;
                    *(float4*)(S + OFF_A + 1760 + r * 40 + g4) = on;
                } else {
                    const float* p = S + OFF_GO + r * 44 + 36;
                    float4 A = *(const float4*)p;
                    float4 Bv = *(const float4*)(p + 4);
                    float t0=A.x,t1=A.y,t2=A.z,t3=A.w,t4=Bv.x,t5=Bv.y,t6=Bv.z,t7=Bv.w;
                    float c6x = fmaxf(fmaxf(t1,t2),fmaxf(fmaxf(t3,t4),fmaxf(t5,t6)));
                    float c6n = fminf(fminf(t1,t2),fminf(fminf(t3,t4),fminf(t5,t6)));
                    S[OFF_A + r * 40 + 36] = fmaxf(c6x, t0);
                    S[OFF_A + r * 40 + 37] = fmaxf(c6x, t7);
                    S[OFF_A + 1760 + r * 40 + 36] = fminf(c6n, t0);
                    S[OFF_A + 1760 + r * 40 + 37] = fminf(c6n, t7);
                }
            }
            __syncthreads();

            // ======== P5: m7 (38x38 v, masked) ; v17 -> registers ========
            #pragma unroll
            for (int idx = tid; idx < 380; idx += NT) {  // 10 row-groups x 38 cols
                int rg = idx / 38, c = idx - rg * 38;
                int r0 = min(rg * 4, 34);
                int gx = X0 - 3 + c;
                bool inx = (unsigned)gx < (unsigned)W;
                int gyb = Y0 - 3 + r0;
                bool i0 = inx && (unsigned)(gyb + 0) < (unsigned)H;
                bool i1 = inx && (unsigned)(gyb + 1) < (unsigned)H;
                bool i2 = inx && (unsigned)(gyb + 2) < (unsigned)H;
                bool i3 = inx && (unsigned)(gyb + 3) < (unsigned)H;
                {
                    float t[10];
                    #pragma unroll
                    for (int q = 0; q < 10; ++q) t[q] = S[OFF_A + (r0 + q) * 40 + c];
                    float cx = fmaxf(fmaxf(t[3],t[4]),fmaxf(t[5],t[6]));
                    float o0 = fmaxf(fmaxf(fmaxf(cx,t[0]),t[1]),t[2]);
                    float o1 = fmaxf(fmaxf(fmaxf(cx,t[1]),t[2]),t[7]);
                    float o2 = fmaxf(fmaxf(fmaxf(cx,t[2]),t[7]),t[8]);
                    float o3 = fmaxf(fmaxf(fmaxf(cx,t[7]),t[8]),t[9]);
                    S[OFF_C + (r0 + 0) * 40 + c] = i0 ? o0 : 0.f;
                    S[OFF_C + (r0 + 1) * 40 + c] = i1 ? o1 : 0.f;
                    S[OFF_C + (r0 + 2) * 40 + c] = i2 ? o2 : 0.f;
                    S[OFF_C + (r0 + 3) * 40 + c] = i3 ? o3 : 0.f;
                }
                {
                    float t[10];
                    #pragma unroll
                    for (int q = 0; q < 10; ++q) t[q] = S[OFF_A + 1760 + (r0 + q) * 40 + c];
                    float cn = fminf(fminf(t[3],t[4]),fminf(t[5],t[6]));
                    float o0 = fminf(fminf(fminf(cn,t[0]),t[1]),t[2]);
                    float o1 = fminf(fminf(fminf(cn,t[1]),t[2]),t[7]);
                    float o2 = fminf(fminf(fminf(cn,t[2]),t[7]),t[8]);
                    float o3 = fminf(fminf(fminf(cn,t[7]),t[8]),t[9]);
                    S[OFF_C + 1520 + (r0 + 0) * 40 + c] = i0 ? o0 : 0.f;
                    S[OFF_C + 1520 + (r0 + 1) * 40 + c] = i1 ? o1 : 0.f;
                    S[OFF_C + 1520 + (r0 + 2) * 40 + c] = i2 ? o2 : 0.f;
                    S[OFF_C + 1520 + (r0 + 3) * 40 + c] = i3 ? o3 : 0.f;
                }
            }
            if (tid < 256) {  // v17: 8 row-groups x 32 cols -> registers
                int rg = tid >> 5, c = tid & 31;
                int r0 = rg * 4;
                int gx = X0 + c;
                float cntx = (float)(min(gx + 8, W - 1) - max(gx - 8, 0) + 1);
                float inv[4];
                #pragma unroll
                for (int j = 0; j < 4; ++j) {
                    int gy = Y0 + r0 + j;
                    float cnty = (float)(min(gy + 8, H - 1) - max(gy - 8, 0) + 1);
                    inv[j] = __fdividef(1.f, cntx * cnty);
                }
                {
                    float t[20];
                    #pragma unroll
                    for (int q = 0; q < 20; ++q) t[q] = S[OFF_B + (r0 + q) * 32 + c];
                    float s0 = 0.f;
                    #pragma unroll
                    for (int q = 0; q < 17; ++q) s0 += t[q];
                    float s1 = s0 - t[0] + t[17];
                    float s2 = s1 - t[1] + t[18];
                    float s3 = s2 - t[2] + t[19];
                    gmv[0] = s0 * inv[0]; gmv[1] = s1 * inv[1];
                    gmv[2] = s2 * inv[2]; gmv[3] = s3 * inv[3];
                }
                {
                    float t[20];
                    #pragma unroll
                    for (int q = 0; q < 20; ++q) t[q] = S[OFF_B + 1536 + (r0 + q) * 32 + c];
                    float s0 = 0.f;
                    #pragma unroll
                    for (int q = 0; q < 17; ++q) s0 += t[q];
                    float s1 = s0 - t[0] + t[17];
                    float s2 = s1 - t[1] + t[18];
                    float s3 = s2 - t[2] + t[19];
                    gnv[0] = s0 * inv[0]; gnv[1] = s1 * inv[1];
                    gnv[2] = s2 * inv[2]; gnv[3] = s3 * inv[3];
                }
            }
            __syncthreads();

            // ======== P6: h7s (38x32) ========
            #pragma unroll
            for (int idx = tid; idx < 304; idx += NT) {  // 38 rows x 8 groups
                int r = idx / 8, g4 = (idx & 7) * 4;
                {
                    const float* p = S + OFF_C + r * 40 + g4;
                    float4 A = *(const float4*)p;
                    float4 Bv = *(const float4*)(p + 4);
                    float4 Cv = *(const float4*)(p + 8);
                    float t0=A.x,t1=A.y,t2=A.z,t3=A.w,t4=Bv.x,t5=Bv.y,t6=Bv.z,t7=Bv.w,t8=Cv.x,t9=Cv.y;
                    float s0 = t0+t1+t2+t3+t4+t5+t6;
                    float s1 = s0 - t0 + t7;
                    float s2 = s1 - t1 + t8;
                    float s3 = s2 - t2 + t9;
                    *(float4*)(S + OFF_A + r * 32 + g4) = make_float4(s0, s1, s2, s3);
                }
                {
                    const float* p = S + OFF_C + 1520 + r * 40 + g4;
                    float4 A = *(const float4*)p;
                    float4 Bv = *(const float4*)(p + 4);
                    float4 Cv = *(const float4*)(p + 8);
                    float t0=A.x,t1=A.y,t2=A.z,t3=A.w,t4=Bv.x,t5=Bv.y,t6=Bv.z,t7=Bv.w,t8=Cv.x,t9=Cv.y;
                    float s0 = t0+t1+t2+t3+t4+t5+t6;
                    float s1 = s0 - t0 + t7;
                    float s2 = s1 - t1 + t8;
                    float s3 = s2 - t2 + t9;
                    *(float4*)(S + OFF_A + 1216 + r * 32 + g4) = make_float4(s0, s1, s2, s3);
                }
            }
            __syncthreads();

            // ======== P7: final (32x32), tid<256, same mapping as v17 ========
            if (tid < 256) {
                int rg = tid >> 5, c = tid & 31;
                int r0 = rg * 4;
                float sA[4], sD[4];
                {
                    float t[10];
                    #pragma unroll
                    for (int q = 0; q < 10; ++q) t[q] = S[OFF_A + (r0 + q) * 32 + c];
                    sA[0] = t[0]+t[1]+t[2]+t[3]+t[4]+t[5]+t[6];
                    sA[1] = sA[0] - t[0] + t[7];
                    sA[2] = sA[1] - t[1] + t[8];
                    sA[3] = sA[2] - t[2] + t[9];
                }
                {
                    float t[10];
                    #pragma unroll
                    for (int q = 0; q < 10; ++q) t[q] = S[OFF_A + 1216 + (r0 + q) * 32 + c];
                    sD[0] = t[0]+t[1]+t[2]+t[3]+t[4]+t[5]+t[6];
                    sD[1] = sD[0] - t[0] + t[7];
                    sD[2] = sD[1] - t[1] + t[8];
                    sD[3] = sD[2] - t[2] + t[9];
                }
                int gx = X0 + c;
                float cntx = (float)(min(gx + 3, W - 1) - max(gx - 3, 0) + 1);
                #pragma unroll
                for (int j = 0; j < 4; ++j) {
                    int gy = Y0 + r0 + j;
                    float cnty = (float)(min(gy + 3, H - 1) - max(gy - 3, 0) + 1);
                    float inv = __fdividef(1.f, cntx * cnty);
                    float pmax = sA[j] * inv, pmin = sD[j] * inv;
                    float go = S[OFF_GO + (r0 + j + 6) * 44 + c + 6];
                    float ga = S[OFF_SGA + (r0 + j + 12) * 56 + c + 12];
                    float gn = __fdividef(go - pmin, fabsf(pmax - pmin) + EPSF);
                    float gn1 = __fdividef(ga - gnv[j], fabsf(gmv[j] - gnv[j]) + EPSF);
                    float val = (gn + 0.01f) * gn1;
                    if (img == 0) {
                        vsave[dir][j] = val;
                    } else {
                        float rv = vsave[dir][j];
                        acc += (double)(rv * expf(-10.f * (rv + val)));
                    }
                }
            }
            __syncthreads();
        }
    }

    // ---- block reduction (16 warps) ----
    int tx = tid & 31, ty = tid >> 5;
    #pragma unroll
    for (int off = 16; off; off >>= 1) acc += __shfl_down_sync(0xffffffffu, acc, off);
    if (tx == 0) sred[ty] = acc;
    __syncthreads();
    if (ty == 0 && tx < NT / 32) {
        double w = sred[tx];
        #pragma unroll
        for (int off = (NT / 64); off; off >>= 1) w += __shfl_down_sync(0xffffffffu, w, off);
        if (tx == 0) atomicAdd(&g_acc, w);
    }
}

__global__ void k_out(float* __restrict__ out) {
    out[0] = (float)(g_acc / (double)NMAP);
}

extern "C" void kernel_launch(void* const* d_in, const int* in_sizes, int n_in,
                              void* d_out, int out_size) {
    const float* R_low = (const float*)d_in[0];
    const float* low = (const float*)d_in[1];
    float* out = (float*)d_out;

    cudaFuncSetAttribute(k_mega, cudaFuncAttributeMaxDynamicSharedMemorySize, SMEM_BYTES);

    float* grayR;
    cudaGetSymbolAddress((void**)&grayR, g_gray);
    float* grayL = grayR + NMAP;

    int gray_blocks = (NMAP / 4 + 255) / 256;

    k_zero<<<1, 1>>>();
    k_gray<<<gray_blocks, 256>>>(R_low, grayR);
    k_gray<<<gray_blocks, 256>>>(low, grayL);

    dim3 grd(16, 16, 16);
    k_mega<<<grd, NT, SMEM_BYTES>>>();

    k_out<<<1, 1>>>(out);
}